// round 2
// baseline (speedup 1.0000x reference)
#include <cuda_runtime.h>
#include <cuda_bf16.h>
#include <math.h>

// Problem constants
#define T_  256
#define B_  128
#define F_  1024
#define U_  512
#define G4U 2048   // 4*U
#define CODES_ 1024
#define MB_ (T_*B_)   // 32768 rows

// Scratch (device globals; no allocation allowed)
__device__ float g_xz[(size_t)MB_ * G4U];       // 256 MB: x@W_in + b
__device__ float g_hseq[(size_t)MB_ * U_];      // 64 MB: masked h sequence
__device__ float g_logits[(size_t)MB_ * CODES_];// 128 MB
__device__ float g_h[B_ * U_];
__device__ float g_c[B_ * U_];
#define KSPLIT 8
__device__ float g_zpart[KSPLIT * B_ * G4U];    // 8 MB

// ---------------------------------------------------------------------------
// Generic fp32 SGEMM: C = A(MxK) * B(KxN) [+bias] [relu]
// BM=BN=128, BK=16, 8x8 per thread, 256 threads.
// K-split via blockIdx.z: each z-slice computes a partial over Kc columns of A
// starting at z*Kc, writing to its own slab C + z*M*ldc.
// ---------------------------------------------------------------------------
#define BM 128
#define BN 128
#define BK 16
#define TM 8
#define TN 8

__global__ __launch_bounds__(256) void sgemm_kernel(
    const float* __restrict__ A, const float* __restrict__ Bm,
    const float* __restrict__ bias, float* __restrict__ C,
    int M, int N, int Kc, int lda, int ldb, int ldc, int relu)
{
    const int kc = blockIdx.z;
    A  += (size_t)kc * Kc;            // column offset into A
    Bm += (size_t)kc * Kc * ldb;      // row offset into B
    C  += (size_t)kc * M * ldc;       // partial slab

    const int bm = blockIdx.y * BM;
    const int bn = blockIdx.x * BN;

    __shared__ float As[BK][BM];
    __shared__ float Bs[BK][BN];

    const int tid = threadIdx.x;
    const int tx = tid & 15;
    const int ty = tid >> 4;

    float acc[TM][TN];
    #pragma unroll
    for (int i = 0; i < TM; i++)
        #pragma unroll
        for (int j = 0; j < TN; j++) acc[i][j] = 0.f;

    for (int k0 = 0; k0 < Kc; k0 += BK) {
        // Load A tile: BM x BK = 2048 floats = 512 float4
        #pragma unroll
        for (int i = 0; i < 2; i++) {
            int lin = tid + i * 256;          // float4 index
            int row = lin >> 2;               // 4 float4 per row
            int kq  = (lin & 3) << 2;
            float4 v = *(const float4*)(A + (size_t)(bm + row) * lda + k0 + kq);
            As[kq + 0][row] = v.x;
            As[kq + 1][row] = v.y;
            As[kq + 2][row] = v.z;
            As[kq + 3][row] = v.w;
        }
        // Load B tile: BK x BN = 2048 floats = 512 float4
        #pragma unroll
        for (int i = 0; i < 2; i++) {
            int lin = tid + i * 256;
            int kr = lin >> 5;                // 32 float4 per row
            int nq = (lin & 31) << 2;
            *(float4*)(&Bs[kr][nq]) =
                *(const float4*)(Bm + (size_t)(k0 + kr) * ldb + bn + nq);
        }
        __syncthreads();

        #pragma unroll
        for (int kk = 0; kk < BK; kk++) {
            float a[TM], b[TN];
            #pragma unroll
            for (int i = 0; i < TM; i++) a[i] = As[kk][ty * TM + i];
            #pragma unroll
            for (int j = 0; j < TN; j++) b[j] = Bs[kk][tx * TN + j];
            #pragma unroll
            for (int i = 0; i < TM; i++)
                #pragma unroll
                for (int j = 0; j < TN; j++)
                    acc[i][j] += a[i] * b[j];
        }
        __syncthreads();
    }

    // Epilogue
    #pragma unroll
    for (int i = 0; i < TM; i++) {
        int r = bm + ty * TM + i;
        #pragma unroll
        for (int j = 0; j < TN; j += 4) {
            int cidx = bn + tx * TN + j;
            float4 v;
            v.x = acc[i][j + 0];
            v.y = acc[i][j + 1];
            v.z = acc[i][j + 2];
            v.w = acc[i][j + 3];
            if (bias) {
                v.x += bias[cidx + 0]; v.y += bias[cidx + 1];
                v.z += bias[cidx + 2]; v.w += bias[cidx + 3];
            }
            if (relu) {
                v.x = fmaxf(v.x, 0.f); v.y = fmaxf(v.y, 0.f);
                v.z = fmaxf(v.z, 0.f); v.w = fmaxf(v.w, 0.f);
            }
            *(float4*)(C + (size_t)r * ldc + cidx) = v;
        }
    }
}

// ---------------------------------------------------------------------------
// Per-step gate fusion: z = xz_t + sum_s zpart[s]; gates; update c,h;
// write masked h into hseq slab for step t.
// ---------------------------------------------------------------------------
__global__ void lstm_gates_kernel(
    const float* __restrict__ xz_t,    // [B][4U]
    const float* __restrict__ zpart,   // [KSPLIT][B][4U]
    const float* __restrict__ mask_t,  // [B]
    float* __restrict__ h, float* __restrict__ c,
    float* __restrict__ hseq_t)        // [B][U]
{
    int idx = blockIdx.x * blockDim.x + threadIdx.x;   // 0..B*U-1
    int b = idx >> 9;          // /512
    int u = idx & 511;

    const float* xb = xz_t + (size_t)b * G4U;
    float zi = xb[u];
    float zf = xb[u + 512];
    float zg = xb[u + 1024];
    float zo = xb[u + 1536];
    #pragma unroll
    for (int s = 0; s < KSPLIT; s++) {
        const float* p = zpart + (size_t)s * B_ * G4U + (size_t)b * G4U;
        zi += p[u];
        zf += p[u + 512];
        zg += p[u + 1024];
        zo += p[u + 1536];
    }
    float ig = 1.f / (1.f + expf(-zi));
    float fg = 1.f / (1.f + expf(-zf));
    float gg = tanhf(zg);
    float og = 1.f / (1.f + expf(-zo));
    float cn = fg * c[idx] + ig * gg;
    float hn = og * tanhf(cn);
    c[idx] = cn;
    h[idx] = hn;
    hseq_t[idx] = hn * mask_t[b];
}

// ---------------------------------------------------------------------------
// Zero h, c
// ---------------------------------------------------------------------------
__global__ void zero_state_kernel(float* __restrict__ h, float* __restrict__ c)
{
    int idx = blockIdx.x * blockDim.x + threadIdx.x;
    if (idx < B_ * U_) { h[idx] = 0.f; c[idx] = 0.f; }
}

// ---------------------------------------------------------------------------
// Row softmax over CODES=1024, 256 threads/block (4 elems/thread)
// ---------------------------------------------------------------------------
__global__ __launch_bounds__(256) void softmax_kernel(
    const float* __restrict__ logits, float* __restrict__ out)
{
    const int row = blockIdx.x;
    const float* in = logits + (size_t)row * CODES_;
    float* o = out + (size_t)row * CODES_;
    __shared__ float red[8];

    const int tid = threadIdx.x;
    float v[4];
    float lmax = -INFINITY;
    #pragma unroll
    for (int j = 0; j < 4; j++) {
        v[j] = in[tid + j * 256];
        lmax = fmaxf(lmax, v[j]);
    }
    #pragma unroll
    for (int off = 16; off; off >>= 1)
        lmax = fmaxf(lmax, __shfl_xor_sync(0xFFFFFFFFu, lmax, off));
    if ((tid & 31) == 0) red[tid >> 5] = lmax;
    __syncthreads();
    float m = red[0];
    #pragma unroll
    for (int k = 1; k < 8; k++) m = fmaxf(m, red[k]);
    __syncthreads();

    float s = 0.f;
    #pragma unroll
    for (int j = 0; j < 4; j++) {
        v[j] = expf(v[j] - m);
        s += v[j];
    }
    #pragma unroll
    for (int off = 16; off; off >>= 1)
        s += __shfl_xor_sync(0xFFFFFFFFu, s, off);
    if ((tid & 31) == 0) red[tid >> 5] = s;
    __syncthreads();
    float tot = 0.f;
    #pragma unroll
    for (int k = 0; k < 8; k++) tot += red[k];
    float inv = 1.f / tot;
    #pragma unroll
    for (int j = 0; j < 4; j++) o[tid + j * 256] = v[j] * inv;
}

// ---------------------------------------------------------------------------
// Host launch
// ---------------------------------------------------------------------------
extern "C" void kernel_launch(void* const* d_in, const int* in_sizes, int n_in,
                              void* d_out, int out_size)
{
    const float* x       = (const float*)d_in[0];   // [T,B,F]
    const float* mask    = (const float*)d_in[1];   // [T,B]
    const float* W_in    = (const float*)d_in[2];   // [F,4U]
    const float* W_rec   = (const float*)d_in[3];   // [U,4U]
    const float* b_lstm  = (const float*)d_in[4];   // [4U]
    const float* W_dense = (const float*)d_in[5];   // [U,CODES]
    const float* b_dense = (const float*)d_in[6];   // [CODES]
    float* out = (float*)d_out;

    static float *xz = nullptr, *hseq, *logits, *h, *c, *zpart;
    if (!xz) {
        cudaGetSymbolAddress((void**)&xz,     g_xz);
        cudaGetSymbolAddress((void**)&hseq,   g_hseq);
        cudaGetSymbolAddress((void**)&logits, g_logits);
        cudaGetSymbolAddress((void**)&h,      g_h);
        cudaGetSymbolAddress((void**)&c,      g_c);
        cudaGetSymbolAddress((void**)&zpart,  g_zpart);
    }

    // 0. zero recurrent state
    zero_state_kernel<<<(B_ * U_ + 255) / 256, 256>>>(h, c);

    // 1. xz = x @ W_in + b_lstm    : M=32768, N=2048, K=1024
    {
        dim3 grid(G4U / BN, MB_ / BM, 1);
        sgemm_kernel<<<grid, 256>>>(x, W_in, b_lstm, xz,
                                    MB_, G4U, F_, F_, G4U, G4U, 0);
    }

    // 2. recurrence
    for (int t = 0; t < T_; t++) {
        // zpart[s] = h @ W_rec (K split into 8 chunks of 64)
        dim3 gs(G4U / BN, 1, KSPLIT);
        sgemm_kernel<<<gs, 256>>>(h, W_rec, nullptr, zpart,
                                  B_, G4U, U_ / KSPLIT, U_, G4U, G4U, 0);
        lstm_gates_kernel<<<(B_ * U_) / 256, 256>>>(
            xz + (size_t)t * B_ * G4U, zpart, mask + (size_t)t * B_,
            h, c, hseq + (size_t)t * B_ * U_);
    }

    // 3. logits = relu(hseq @ W_dense + b_dense) : M=32768, N=1024, K=512
    {
        dim3 grid(CODES_ / BN, MB_ / BM, 1);
        sgemm_kernel<<<grid, 256>>>(hseq, W_dense, b_dense, logits,
                                    MB_, CODES_, U_, U_, CODES_, CODES_, 1);
    }

    // 4. softmax rows -> out
    softmax_kernel<<<MB_, 256>>>(logits, out);
}